// round 9
// baseline (speedup 1.0000x reference)
#include <cuda_runtime.h>
#include <cuda_fp16.h>
#include <cstdint>

// TT layer via merged-core fp16 mma.sync GEMMs (m16n8k16, fp32 accumulate).
// Round 9: 128-thread CTAs (4 warps, 64x128 tile, 4 CTAs/SM) for more
// independent barrier domains; same ldmatrix + 3-stage cp.async pipeline.
// out[n,ab,cd] = relu( sum H12[ab,(s,ij)] x[n,ij,kl] H34[(cd,s),kl] + bias )
// GEMM1 per n: M1[cds, ij] = H34 . Xr[n]^T   M=1024 N=256 K=256
// GEMM2 per n: out[ab, cd] = H12 . M1[n]^T   M=256  N=256 K=1024 (+bias,relu)

__device__ __half g_H34[262144];
__device__ __half g_H12[262144];
__device__ __half g_Xr[67108864];   // RNE-rounded x (128 MB)
__device__ __half g_M1[268435456];  // M1 fp16 (512 MB)

__device__ __forceinline__ uint32_t smem_u32(const void* p) {
  uint32_t a;
  asm("{ .reg .u64 t; cvta.to.shared.u64 t, %1; cvt.u32.u64 %0, t; }" : "=r"(a) : "l"(p));
  return a;
}
__device__ __forceinline__ void cp16(uint32_t s, const __half* g) {
  asm volatile("cp.async.cg.shared.global [%0], [%1], 16;" :: "r"(s), "l"(g));
}
__device__ __forceinline__ void mma_f16(float* c, const uint32_t* a, uint32_t b0, uint32_t b1) {
  asm volatile(
      "mma.sync.aligned.m16n8k16.row.col.f32.f16.f16.f32 "
      "{%0,%1,%2,%3}, {%4,%5,%6,%7}, {%8,%9}, {%0,%1,%2,%3};"
      : "+f"(c[0]), "+f"(c[1]), "+f"(c[2]), "+f"(c[3])
      : "r"(a[0]), "r"(a[1]), "r"(a[2]), "r"(a[3]), "r"(b0), "r"(b1));
}
__device__ __forceinline__ void ldsm_x4(uint32_t* r, uint32_t addr) {
  asm volatile("ldmatrix.sync.aligned.m8n8.x4.shared.b16 {%0,%1,%2,%3}, [%4];"
               : "=r"(r[0]), "=r"(r[1]), "=r"(r[2]), "=r"(r[3]) : "r"(addr));
}

// ---------------- precompute (fp32 math, RNE fp16 store) ----------------
__global__ void prep_h34(const float* __restrict__ G3, const float* __restrict__ G4) {
  int e = blockIdx.x * 256 + threadIdx.x;
  int col = e & 255, row = e >> 8;
  int s = row & 3, cd = row >> 2;
  int c = cd >> 4, d = cd & 15, k = col >> 4, l = col & 15;
  float acc = 0.f;
#pragma unroll
  for (int tt = 0; tt < 4; ++tt)
    acc += G3[((c * 16 + k) * 4 + s) * 4 + tt] * G4[(d * 16 + l) * 4 + tt];
  g_H34[e] = __float2half_rn(acc);
}
__global__ void prep_h12(const float* __restrict__ G1, const float* __restrict__ G2) {
  int e = blockIdx.x * 256 + threadIdx.x;
  int ab = e >> 10, k = e & 1023;
  int s = k >> 8, ij = k & 255;
  int a = ab >> 4, b = ab & 15, i = ij >> 4, j = ij & 15;
  float acc = 0.f;
#pragma unroll
  for (int r = 0; r < 4; ++r)
    acc += G1[(a * 16 + i) * 4 + r] * G2[((b * 16 + j) * 4 + r) * 4 + s];
  g_H12[e] = __float2half_rn(acc);
}
__global__ __launch_bounds__(256) void round_x(const float* __restrict__ x) {
  size_t idx = (size_t)blockIdx.x * 256 + threadIdx.x;
  float4 v = *(const float4*)(x + idx * 4);
  __half2 h0 = __floats2half2_rn(v.x, v.y);
  __half2 h1 = __floats2half2_rn(v.z, v.w);
  uint2 o = { *(uint32_t*)&h0, *(uint32_t*)&h1 };
  *(uint2*)(g_Xr + idx * 4) = o;
}

// ---------------- batched fp16 GEMM: C[n] = A . B[n]^T ----------------
// A [Mtotal x K] K-major half; B[n] [256 x K] K-major half.
// C[n]: fp32 (bias+relu) if bias != null, else fp16.
// CTA 64x128, 4 warps of 32(m) x 64(n). K-chunk 32, 3-stage cp.async.
#define PADH 40
#define A_TILE_H 2560   // 64 * PADH halves
#define B_TILE_H 5120   // 128 * PADH halves
#define STG_H 7680      // halves per stage (A + B)

__global__ __launch_bounds__(128, 4) void tt_gemm(
    const __half* __restrict__ A, const __half* __restrict__ Bbase, long long bStride,
    void* __restrict__ Cbase, long long cStride, int K,
    const float* __restrict__ bias) {
  extern __shared__ __align__(16) __half smh[];
  const int t = threadIdx.x;
  const int lane = t & 31, wid = t >> 5;
  const int grp = lane >> 2, tg = lane & 3;
  const int nt = blockIdx.x & 1, mt = blockIdx.x >> 1;
  const int n = blockIdx.y;
  const int wm = (wid & 1) * 32, wn = (wid >> 1) * 64;

  const __half* Am = A + (long long)mt * 64 * K;
  const __half* Bn = Bbase + (long long)n * bStride + (long long)nt * 128 * K;

  // cp.async mapping: 32 halves/row = 4 segs of 16B. srow = t>>2, sq = t&3.
  // A: 64 rows = 2 reps (+32); B: 128 rows = 4 reps (+32).
  const int srow = t >> 2, sq = t & 3;
  const uint32_t base = smem_u32(smh);
  const uint32_t stA = base + (uint32_t)(srow * PADH + sq * 8) * 2u;
  const uint32_t stB = stA + A_TILE_H * 2u;

  // ldmatrix per-lane base offsets (bytes from stage base)
  uint32_t aOff[2];
#pragma unroll
  for (int mi = 0; mi < 2; ++mi)
    aOff[mi] = (uint32_t)((wm + mi * 16 + (lane & 15)) * PADH + (lane >> 4) * 8) * 2u;
  uint32_t bOff[4];
#pragma unroll
  for (int q = 0; q < 4; ++q)
    bOff[q] = (uint32_t)((wn + q * 16 + (lane & 7) + ((lane >> 4) << 3)) * PADH +
                         (((lane >> 3) & 1) << 3)) * 2u + A_TILE_H * 2u;

  float acc[2][8][4];
#pragma unroll
  for (int mi = 0; mi < 2; ++mi)
#pragma unroll
    for (int ni = 0; ni < 8; ++ni)
#pragma unroll
      for (int q = 0; q < 4; ++q) acc[mi][ni][q] = 0.f;

  const int nch = K >> 5;

  // prologue: chunks 0,1 -> stages 0,1
#pragma unroll
  for (int pch = 0; pch < 2; ++pch) {
    const __half* ga = Am + pch * 32;
    const __half* gb = Bn + pch * 32;
    const uint32_t so = (uint32_t)pch * STG_H * 2u;
#pragma unroll
    for (int rep = 0; rep < 2; ++rep)
      cp16(stA + so + rep * 32u * PADH * 2u, ga + (long long)(srow + rep * 32) * K + sq * 8);
#pragma unroll
    for (int rep = 0; rep < 4; ++rep)
      cp16(stB + so + rep * 32u * PADH * 2u, gb + (long long)(srow + rep * 32) * K + sq * 8);
    asm volatile("cp.async.commit_group;" ::: "memory");
  }

  int st = 0, pst = 2;
  for (int ch = 0; ch < nch; ++ch) {
    asm volatile("cp.async.wait_group 1;" ::: "memory");
    __syncthreads();

    if (ch + 2 < nch) {
      const __half* ga = Am + (ch + 2) * 32;
      const __half* gb = Bn + (ch + 2) * 32;
      const uint32_t so = (uint32_t)pst * STG_H * 2u;
#pragma unroll
      for (int rep = 0; rep < 2; ++rep)
        cp16(stA + so + rep * 32u * PADH * 2u, ga + (long long)(srow + rep * 32) * K + sq * 8);
#pragma unroll
      for (int rep = 0; rep < 4; ++rep)
        cp16(stB + so + rep * 32u * PADH * 2u, gb + (long long)(srow + rep * 32) * K + sq * 8);
    }
    asm volatile("cp.async.commit_group;" ::: "memory");

    const uint32_t sbase = base + (uint32_t)st * STG_H * 2u;
#pragma unroll
    for (int sel = 0; sel < 2; ++sel) {
      const uint32_t ko = (uint32_t)sel * 32u;  // 16 halves
      uint32_t a[2][4], b[4][4];
      ldsm_x4(a[0], sbase + aOff[0] + ko);
      ldsm_x4(a[1], sbase + aOff[1] + ko);
#pragma unroll
      for (int q = 0; q < 4; ++q) ldsm_x4(b[q], sbase + bOff[q] + ko);
#pragma unroll
      for (int q = 0; q < 4; ++q) {
#pragma unroll
        for (int mi = 0; mi < 2; ++mi) {
          mma_f16(acc[mi][2 * q],     a[mi], b[q][0], b[q][1]);
          mma_f16(acc[mi][2 * q + 1], a[mi], b[q][2], b[q][3]);
        }
      }
    }
    st = st == 2 ? 0 : st + 1;
    pst = pst == 2 ? 0 : pst + 1;
  }

  if (bias) {
    float* Cn = (float*)Cbase + (long long)n * cStride;
#pragma unroll
    for (int mi = 0; mi < 2; ++mi) {
      int r0 = mt * 64 + wm + mi * 16 + grp;
#pragma unroll
      for (int ni = 0; ni < 8; ++ni) {
        int col = nt * 128 + wn + ni * 8 + 2 * tg;
        float v0 = fmaxf(acc[mi][ni][0] + bias[r0 * 256 + col], 0.f);
        float v1 = fmaxf(acc[mi][ni][1] + bias[r0 * 256 + col + 1], 0.f);
        float v2 = fmaxf(acc[mi][ni][2] + bias[(r0 + 8) * 256 + col], 0.f);
        float v3 = fmaxf(acc[mi][ni][3] + bias[(r0 + 8) * 256 + col + 1], 0.f);
        *(float2*)(Cn + (long long)r0 * 256 + col) = make_float2(v0, v1);
        *(float2*)(Cn + (long long)(r0 + 8) * 256 + col) = make_float2(v2, v3);
      }
    }
  } else {
    __half* Cn = (__half*)Cbase + (long long)n * cStride;
#pragma unroll
    for (int mi = 0; mi < 2; ++mi) {
      int r0 = mt * 64 + wm + mi * 16 + grp;
#pragma unroll
      for (int ni = 0; ni < 8; ++ni) {
        int col = nt * 128 + wn + ni * 8 + 2 * tg;
        __half2 h01 = __floats2half2_rn(acc[mi][ni][0], acc[mi][ni][1]);
        __half2 h23 = __floats2half2_rn(acc[mi][ni][2], acc[mi][ni][3]);
        *(uint32_t*)(Cn + (long long)r0 * 256 + col) = *(uint32_t*)&h01;
        *(uint32_t*)(Cn + (long long)(r0 + 8) * 256 + col) = *(uint32_t*)&h23;
      }
    }
  }
}

// ---------------- launch ----------------
extern "C" void kernel_launch(void* const* d_in, const int* in_sizes, int n_in,
                              void* d_out, int out_size) {
  const float* x    = (const float*)d_in[0];
  const float* G1   = (const float*)d_in[1];
  const float* G2   = (const float*)d_in[2];
  const float* G3   = (const float*)d_in[3];
  const float* G4   = (const float*)d_in[4];
  const float* bias = (const float*)d_in[5];
  float* out = (float*)d_out;
  const int nb = in_sizes[0] / 65536;

  __half *pH34, *pH12, *pM1, *pXr;
  cudaGetSymbolAddress((void**)&pH34, g_H34);
  cudaGetSymbolAddress((void**)&pH12, g_H12);
  cudaGetSymbolAddress((void**)&pM1, g_M1);
  cudaGetSymbolAddress((void**)&pXr, g_Xr);

  const int smem = 3 * STG_H * 2;  // 46080 B -> 4 CTAs/SM
  cudaFuncSetAttribute(tt_gemm, cudaFuncAttributeMaxDynamicSharedMemorySize, smem);

  prep_h34<<<1024, 256>>>(G3, G4);
  prep_h12<<<1024, 256>>>(G1, G2);
  round_x<<<in_sizes[0] / 1024, 256>>>(x);

  // GEMM1: M1[n] = H34 (1024xK256) . Xr[n]^T : 16 mtiles x 2 ntiles
  tt_gemm<<<dim3(32, nb), 128, smem>>>(pH34, pXr, 65536LL, pM1, 262144LL, 256,
                                       nullptr);
  // GEMM2: out[n] = H12 (256xK1024) . M1[n]^T : 4 mtiles x 2 ntiles (+bias,relu)
  tt_gemm<<<dim3(8, nb), 128, smem>>>(pH12, pM1, 262144LL, out, 65536LL, 1024,
                                      bias);
}

// round 10
// speedup vs baseline: 1.1365x; 1.1365x over previous
#include <cuda_runtime.h>
#include <cuda_fp16.h>
#include <cstdint>

// TT layer via merged-core fp16 mma.sync GEMMs (m16n8k16, fp32 accumulate).
// Round 10: GEMM1 keeps A (H34 tile) resident in smem and loops 8 samples per
// CTA with a continuous 4-stage B pipeline; GEMM2 gets a 4-stage pipeline.
// out[n,ab,cd] = relu( sum H12[ab,(s,ij)] x[n,ij,kl] H34[(cd,s),kl] + bias )
// GEMM1 per n: M1[cds, ij] = H34 . Xr[n]^T   M=1024 N=256 K=256
// GEMM2 per n: out[ab, cd] = H12 . M1[n]^T   M=256  N=256 K=1024 (+bias,relu)

__device__ __half g_H34[262144];
__device__ __half g_H12[262144];
__device__ __half g_Xr[67108864];   // RNE-rounded x (128 MB)
__device__ __half g_M1[268435456];  // M1 fp16 (512 MB)

__device__ __forceinline__ uint32_t smem_u32(const void* p) {
  uint32_t a;
  asm("{ .reg .u64 t; cvta.to.shared.u64 t, %1; cvt.u32.u64 %0, t; }" : "=r"(a) : "l"(p));
  return a;
}
__device__ __forceinline__ void cp16(uint32_t s, const __half* g) {
  asm volatile("cp.async.cg.shared.global [%0], [%1], 16;" :: "r"(s), "l"(g));
}
__device__ __forceinline__ void mma_f16(float* c, const uint32_t* a, uint32_t b0, uint32_t b1) {
  asm volatile(
      "mma.sync.aligned.m16n8k16.row.col.f32.f16.f16.f32 "
      "{%0,%1,%2,%3}, {%4,%5,%6,%7}, {%8,%9}, {%0,%1,%2,%3};"
      : "+f"(c[0]), "+f"(c[1]), "+f"(c[2]), "+f"(c[3])
      : "r"(a[0]), "r"(a[1]), "r"(a[2]), "r"(a[3]), "r"(b0), "r"(b1));
}
__device__ __forceinline__ void ldsm_x4(uint32_t* r, uint32_t addr) {
  asm volatile("ldmatrix.sync.aligned.m8n8.x4.shared.b16 {%0,%1,%2,%3}, [%4];"
               : "=r"(r[0]), "=r"(r[1]), "=r"(r[2]), "=r"(r[3]) : "r"(addr));
}

// ---------------- precompute (fp32 math, RNE fp16 store) ----------------
__global__ void prep_h34(const float* __restrict__ G3, const float* __restrict__ G4) {
  int e = blockIdx.x * 256 + threadIdx.x;
  int col = e & 255, row = e >> 8;
  int s = row & 3, cd = row >> 2;
  int c = cd >> 4, d = cd & 15, k = col >> 4, l = col & 15;
  float acc = 0.f;
#pragma unroll
  for (int tt = 0; tt < 4; ++tt)
    acc += G3[((c * 16 + k) * 4 + s) * 4 + tt] * G4[(d * 16 + l) * 4 + tt];
  g_H34[e] = __float2half_rn(acc);
}
__global__ void prep_h12(const float* __restrict__ G1, const float* __restrict__ G2) {
  int e = blockIdx.x * 256 + threadIdx.x;
  int ab = e >> 10, k = e & 1023;
  int s = k >> 8, ij = k & 255;
  int a = ab >> 4, b = ab & 15, i = ij >> 4, j = ij & 15;
  float acc = 0.f;
#pragma unroll
  for (int r = 0; r < 4; ++r)
    acc += G1[(a * 16 + i) * 4 + r] * G2[((b * 16 + j) * 4 + r) * 4 + s];
  g_H12[e] = __float2half_rn(acc);
}
__global__ __launch_bounds__(256) void round_x(const float* __restrict__ x) {
  size_t idx = (size_t)blockIdx.x * 256 + threadIdx.x;
  float4 v = *(const float4*)(x + idx * 4);
  __half2 h0 = __floats2half2_rn(v.x, v.y);
  __half2 h1 = __floats2half2_rn(v.z, v.w);
  uint2 o = { *(uint32_t*)&h0, *(uint32_t*)&h1 };
  *(uint2*)(g_Xr + idx * 4) = o;
}

#define PADH 40
#define PADA 264          // resident A row stride in halves (256 + 8)
#define A_RES_H 33792     // 128 * PADA
#define B_STG_H 5120      // 128 * PADH halves per B stage
#define NGRP 8            // samples per GEMM1 CTA

// ---------------- GEMM1: M1[n] = H34_mtile . Xr[n]^T, A resident ----------------
// CTA: 8 warps, tile 128(m) x 128(n). K=256 = 8 chunks of 32; 8 n per CTA,
// continuous 64-chunk 4-stage B pipeline.
__global__ __launch_bounds__(256, 2) void tt_gemm1(
    const __half* __restrict__ A, const __half* __restrict__ B,
    __half* __restrict__ C) {
  extern __shared__ __align__(16) __half smh[];
  const int t = threadIdx.x;
  const int lane = t & 31, wid = t >> 5;
  const int grp = lane >> 2, tg = lane & 3;
  const int nt = blockIdx.x & 1, mt = blockIdx.x >> 1;
  const int nbase = blockIdx.y * NGRP;
  const int wm = (wid & 3) * 32, wn = (wid >> 2) * 64;

  const uint32_t base = smem_u32(smh);
  const uint32_t bbase = base + A_RES_H * 2u;

  // ---- load resident A tile: 128 rows x 256 halves ----
  {
    const __half* Am = A + (long long)mt * 128 * 256;
#pragma unroll
    for (int rep = 0; rep < 16; ++rep) {
      int idx = rep * 256 + t;
      int row = idx >> 5, seg = idx & 31;
      cp16(base + (uint32_t)(row * PADA + seg * 8) * 2u, Am + row * 256 + seg * 8);
    }
    asm volatile("cp.async.commit_group;" ::: "memory");
  }

  // ldmatrix offsets
  uint32_t aOff[2];
#pragma unroll
  for (int mi = 0; mi < 2; ++mi)
    aOff[mi] = (uint32_t)((wm + mi * 16 + (lane & 15)) * PADA + (lane >> 4) * 8) * 2u;
  uint32_t bOff[4];
#pragma unroll
  for (int q = 0; q < 4; ++q)
    bOff[q] = (uint32_t)((wn + q * 16 + (lane & 7) + ((lane >> 4) << 3)) * PADH +
                         (((lane >> 3) & 1) << 3)) * 2u;

  // B chunk loader: chunk gc -> n = nbase + (gc>>3), k-offset (gc&7)*32
  const int srow = t >> 2, sq = t & 3;
  const uint32_t stB = bbase + (uint32_t)(srow * PADH + sq * 8) * 2u;
  const __half* Bnt = B + (long long)nt * 128 * 256;

  // prologue: B chunks 0,1,2 -> stages 0,1,2 (groups after A: 3 commits)
#pragma unroll
  for (int pch = 0; pch < 3; ++pch) {
    const __half* gb = Bnt + (long long)(nbase) * 65536 + pch * 32;
    const uint32_t so = (uint32_t)pch * B_STG_H * 2u;
#pragma unroll
    for (int rep = 0; rep < 2; ++rep)
      cp16(stB + so + rep * 64u * PADH * 2u, gb + (long long)(srow + rep * 64) * 256 + sq * 8);
    asm volatile("cp.async.commit_group;" ::: "memory");
  }

  float acc[2][8][4];
#pragma unroll
  for (int mi = 0; mi < 2; ++mi)
#pragma unroll
    for (int ni = 0; ni < 8; ++ni)
#pragma unroll
      for (int q = 0; q < 4; ++q) acc[mi][ni][q] = 0.f;

  for (int gc = 0; gc < 8 * NGRP; ++gc) {
    const int ch = gc & 7;
    asm volatile("cp.async.wait_group 2;" ::: "memory");
    __syncthreads();

    // prefetch chunk gc+3 into stage (gc+3)&3 (read last at iter gc-1)
    if (gc + 3 < 8 * NGRP) {
      int g2 = gc + 3;
      const __half* gb = Bnt + (long long)(nbase + (g2 >> 3)) * 65536 + (g2 & 7) * 32;
      const uint32_t so = (uint32_t)(g2 & 3) * B_STG_H * 2u;
#pragma unroll
      for (int rep = 0; rep < 2; ++rep)
        cp16(stB + so + rep * 64u * PADH * 2u, gb + (long long)(srow + rep * 64) * 256 + sq * 8);
    }
    asm volatile("cp.async.commit_group;" ::: "memory");

    const uint32_t sa = base + (uint32_t)ch * 64u;  // 32 halves k-offset
    const uint32_t sb = bbase + (uint32_t)(gc & 3) * B_STG_H * 2u;
#pragma unroll
    for (int sel = 0; sel < 2; ++sel) {
      const uint32_t ko = (uint32_t)sel * 32u;
      uint32_t a[2][4], b[4][4];
      ldsm_x4(a[0], sa + aOff[0] + ko);
      ldsm_x4(a[1], sa + aOff[1] + ko);
#pragma unroll
      for (int q = 0; q < 4; ++q) ldsm_x4(b[q], sb + bOff[q] + ko);
#pragma unroll
      for (int q = 0; q < 4; ++q) {
#pragma unroll
        for (int mi = 0; mi < 2; ++mi) {
          mma_f16(acc[mi][2 * q],     a[mi], b[q][0], b[q][1]);
          mma_f16(acc[mi][2 * q + 1], a[mi], b[q][2], b[q][3]);
        }
      }
    }

    if (ch == 7) {  // epilogue for sample n, reset accumulators
      const int n = nbase + (gc >> 3);
      __half* Cn = C + (long long)n * 262144;
#pragma unroll
      for (int mi = 0; mi < 2; ++mi) {
        int r0 = mt * 128 + wm + mi * 16 + grp;
#pragma unroll
        for (int ni = 0; ni < 8; ++ni) {
          int col = nt * 128 + wn + ni * 8 + 2 * tg;
          __half2 h01 = __floats2half2_rn(acc[mi][ni][0], acc[mi][ni][1]);
          __half2 h23 = __floats2half2_rn(acc[mi][ni][2], acc[mi][ni][3]);
          *(uint32_t*)(Cn + (long long)r0 * 256 + col) = *(uint32_t*)&h01;
          *(uint32_t*)(Cn + (long long)(r0 + 8) * 256 + col) = *(uint32_t*)&h23;
#pragma unroll
          for (int q = 0; q < 4; ++q) acc[mi][ni][q] = 0.f;
        }
      }
    }
  }
}

// ---------------- GEMM2: out[n] = H12 . M1[n]^T, 4-stage ----------------
#define STG2_H 10240   // halves per stage (A + B, 128 rows each, PADH)

__global__ __launch_bounds__(256, 2) void tt_gemm2(
    const __half* __restrict__ A, const __half* __restrict__ Bbase,
    float* __restrict__ Cbase, const float* __restrict__ bias) {
  extern __shared__ __align__(16) __half smh[];
  const int t = threadIdx.x;
  const int lane = t & 31, wid = t >> 5;
  const int grp = lane >> 2, tg = lane & 3;
  const int nt = blockIdx.x & 1, mt = blockIdx.x >> 1;
  const int n = blockIdx.y;
  const int wm = (wid & 3) * 32, wn = (wid >> 2) * 64;
  const int K = 1024;

  const __half* Am = A + (long long)mt * 128 * K;
  const __half* Bn = Bbase + (long long)n * 262144 + (long long)nt * 128 * K;

  const int srow = t >> 2, sq = t & 3;
  const uint32_t base = smem_u32(smh);
  const uint32_t stA = base + (uint32_t)(srow * PADH + sq * 8) * 2u;
  const uint32_t stB = stA + (uint32_t)128 * PADH * 2u;

  uint32_t aOff[2];
#pragma unroll
  for (int mi = 0; mi < 2; ++mi)
    aOff[mi] = (uint32_t)((wm + mi * 16 + (lane & 15)) * PADH + (lane >> 4) * 8) * 2u;
  uint32_t bOff[4];
#pragma unroll
  for (int q = 0; q < 4; ++q)
    bOff[q] = (uint32_t)((wn + q * 16 + (lane & 7) + ((lane >> 4) << 3)) * PADH +
                         (((lane >> 3) & 1) << 3)) * 2u + (uint32_t)128 * PADH * 2u;

  float acc[2][8][4];
#pragma unroll
  for (int mi = 0; mi < 2; ++mi)
#pragma unroll
    for (int ni = 0; ni < 8; ++ni)
#pragma unroll
      for (int q = 0; q < 4; ++q) acc[mi][ni][q] = 0.f;

  const int nch = K >> 5;  // 32

  // prologue: chunks 0,1,2 -> stages 0,1,2
#pragma unroll
  for (int pch = 0; pch < 3; ++pch) {
    const __half* ga = Am + pch * 32;
    const __half* gb = Bn + pch * 32;
    const uint32_t so = (uint32_t)pch * STG2_H * 2u;
#pragma unroll
    for (int rep = 0; rep < 2; ++rep) {
      cp16(stA + so + rep * 64u * PADH * 2u, ga + (long long)(srow + rep * 64) * K + sq * 8);
      cp16(stB + so + rep * 64u * PADH * 2u, gb + (long long)(srow + rep * 64) * K + sq * 8);
    }
    asm volatile("cp.async.commit_group;" ::: "memory");
  }

  for (int ch = 0; ch < nch; ++ch) {
    asm volatile("cp.async.wait_group 2;" ::: "memory");
    __syncthreads();

    if (ch + 3 < nch) {
      const __half* ga = Am + (ch + 3) * 32;
      const __half* gb = Bn + (ch + 3) * 32;
      const uint32_t so = (uint32_t)((ch + 3) & 3) * STG2_H * 2u;
#pragma unroll
      for (int rep = 0; rep < 2; ++rep) {
        cp16(stA + so + rep * 64u * PADH * 2u, ga + (long long)(srow + rep * 64) * K + sq * 8);
        cp16(stB + so + rep * 64u * PADH * 2u, gb + (long long)(srow + rep * 64) * K + sq * 8);
      }
    }
    asm volatile("cp.async.commit_group;" ::: "memory");

    const uint32_t sbase = base + (uint32_t)(ch & 3) * STG2_H * 2u;
#pragma unroll
    for (int sel = 0; sel < 2; ++sel) {
      const uint32_t ko = (uint32_t)sel * 32u;
      uint32_t a[2][4], b[4][4];
      ldsm_x4(a[0], sbase + aOff[0] + ko);
      ldsm_x4(a[1], sbase + aOff[1] + ko);
#pragma unroll
      for (int q = 0; q < 4; ++q) ldsm_x4(b[q], sbase + bOff[q] + ko);
#pragma unroll
      for (int q = 0; q < 4; ++q) {
#pragma unroll
        for (int mi = 0; mi < 2; ++mi) {
          mma_f16(acc[mi][2 * q],     a[mi], b[q][0], b[q][1]);
          mma_f16(acc[mi][2 * q + 1], a[mi], b[q][2], b[q][3]);
        }
      }
    }
  }

  float* Cn = Cbase + (long long)n * 65536;
#pragma unroll
  for (int mi = 0; mi < 2; ++mi) {
    int r0 = mt * 128 + wm + mi * 16 + grp;
#pragma unroll
    for (int ni = 0; ni < 8; ++ni) {
      int col = nt * 128 + wn + ni * 8 + 2 * tg;
      float v0 = fmaxf(acc[mi][ni][0] + bias[r0 * 256 + col], 0.f);
      float v1 = fmaxf(acc[mi][ni][1] + bias[r0 * 256 + col + 1], 0.f);
      float v2 = fmaxf(acc[mi][ni][2] + bias[(r0 + 8) * 256 + col], 0.f);
      float v3 = fmaxf(acc[mi][ni][3] + bias[(r0 + 8) * 256 + col + 1], 0.f);
      *(float2*)(Cn + (long long)r0 * 256 + col) = make_float2(v0, v1);
      *(float2*)(Cn + (long long)(r0 + 8) * 256 + col) = make_float2(v2, v3);
    }
  }
}

// ---------------- launch ----------------
extern "C" void kernel_launch(void* const* d_in, const int* in_sizes, int n_in,
                              void* d_out, int out_size) {
  const float* x    = (const float*)d_in[0];
  const float* G1   = (const float*)d_in[1];
  const float* G2   = (const float*)d_in[2];
  const float* G3   = (const float*)d_in[3];
  const float* G4   = (const float*)d_in[4];
  const float* bias = (const float*)d_in[5];
  float* out = (float*)d_out;
  const int nb = in_sizes[0] / 65536;

  __half *pH34, *pH12, *pM1, *pXr;
  cudaGetSymbolAddress((void**)&pH34, g_H34);
  cudaGetSymbolAddress((void**)&pH12, g_H12);
  cudaGetSymbolAddress((void**)&pM1, g_M1);
  cudaGetSymbolAddress((void**)&pXr, g_Xr);

  const int smem1 = (A_RES_H + 4 * B_STG_H) * 2;  // 108544 B
  const int smem2 = 4 * STG2_H * 2;               // 81920 B
  cudaFuncSetAttribute(tt_gemm1, cudaFuncAttributeMaxDynamicSharedMemorySize, smem1);
  cudaFuncSetAttribute(tt_gemm2, cudaFuncAttributeMaxDynamicSharedMemorySize, smem2);

  prep_h34<<<1024, 256>>>(G3, G4);
  prep_h12<<<1024, 256>>>(G1, G2);
  round_x<<<in_sizes[0] / 1024, 256>>>(x);

  // GEMM1: grid (8 mtiles x 2 ntiles, nb/8 n-groups)
  tt_gemm1<<<dim3(16, nb / NGRP), 256, smem1>>>(pH34, pXr, pM1);
  // GEMM2: grid (2 mtiles x 2 ntiles, nb)
  tt_gemm2<<<dim3(4, nb), 256, smem2>>>(pH12, pM1, out, bias);
}